// round 8
// baseline (speedup 1.0000x reference)
#include <cuda_runtime.h>

// Performer FAVOR+ feature map — r7: fix projection loader (was loading only
// j<64 of 256 rows; pT columns 64..255 were uninitialized smem).
// out[t,j] = 1/16 * ( exp( (64^-.25 x_t)·P_j - 0.5||x_t||^2 ) + 1e-4 )

#define D_DIM 64
#define J_DIM 256
#define TOK_TILE 64
#define NTHREADS 256

// ---- Blackwell packed f32x2 helpers ----
__device__ __forceinline__ unsigned long long pack2(float lo, float hi) {
    unsigned long long r;
    asm("mov.b64 %0, {%1, %2};" : "=l"(r) : "f"(lo), "f"(hi));
    return r;
}
__device__ __forceinline__ unsigned long long fma2(unsigned long long a,
                                                   unsigned long long b,
                                                   unsigned long long c) {
    unsigned long long d;
    asm("fma.rn.f32x2 %0, %1, %2, %3;" : "=l"(d) : "l"(a), "l"(b), "l"(c));
    return d;
}
__device__ __forceinline__ void unpack2(unsigned long long v, float& lo, float& hi) {
    asm("mov.b64 {%0, %1}, %2;" : "=f"(lo), "=f"(hi) : "l"(v));
}

// Dynamic smem layout:
//   pT  : [64][256] floats  proj transposed, pre-scaled by 64^-0.25   64 KB
//   xsh : [64][64]  floats  x tile (GEMM operand + diag)              16 KB
//   diag: [64]      floats  0.5*||x||^2 per token                     256 B
extern __shared__ float smem_dyn[];

__global__ void __launch_bounds__(NTHREADS, 2)
performer_fm_r7_kernel(const float* __restrict__ x,
                       const float* __restrict__ proj,
                       float* __restrict__ out,
                       int T, int nTiles)
{
    float* pT      = smem_dyn;                       // D_DIM * J_DIM
    float* xsh     = pT + D_DIM * J_DIM;             // TOK_TILE * D_DIM
    float* diag_sh = xsh + TOK_TILE * D_DIM;         // TOK_TILE

    const int tid = threadIdx.x;
    const int tx  = tid & 31;        // feature group: j = tx*8 .. tx*8+7
    const int ty  = tid >> 5;        // token group:  t = ty*8 .. ty*8+7
    const int jb  = tx * 8;
    const int tb  = ty * 8;

    // ---- load FULL projection once per block: one row per thread, transposed
    //      into pT[d][j], pre-scaled by 64^(-1/4). 256 threads x 64 floats = all 16K.
    {
        const float c = 0.35355339059327373f;   // 64^(-1/4)
        const int j = tid;                      // 0..255 — every projection row
        #pragma unroll
        for (int cidx = 0; cidx < 16; ++cidx) { // all 16 d-chunks of this row
            float4 v = *reinterpret_cast<const float4*>(proj + j * D_DIM + cidx * 4);
            pT[(cidx * 4 + 0) * J_DIM + j] = v.x * c;
            pT[(cidx * 4 + 1) * J_DIM + j] = v.y * c;
            pT[(cidx * 4 + 2) * J_DIM + j] = v.z * c;
            pT[(cidx * 4 + 3) * J_DIM + j] = v.w * c;
        }
    }

    for (int tile = blockIdx.x; tile < nTiles; tile += gridDim.x) {
        const int t0 = tile * TOK_TILE;

        __syncthreads();   // pT ready (iter 0) / previous epilogue done with smem

        // ---- load x tile (coalesced) ----
        {
            const int d4 = tid & 15;       // d = d4*4
            const int tl = tid >> 4;       // 0..15
            #pragma unroll
            for (int it = 0; it < 4; ++it) {
                const int t  = tl + it * 16;
                const int gt = t0 + t;
                float4 v = (gt < T)
                    ? *reinterpret_cast<const float4*>(x + (size_t)gt * D_DIM + d4 * 4)
                    : make_float4(0.f, 0.f, 0.f, 0.f);
                *reinterpret_cast<float4*>(&xsh[t * D_DIM + d4 * 4]) = v;
            }
        }
        __syncthreads();

        // ---- diag = 0.5*||x||^2 per token (4 threads / token, full fp32) ----
        {
            const int t    = tid >> 2;
            const int part = tid & 3;
            const float4* row = reinterpret_cast<const float4*>(&xsh[t * D_DIM + part * 16]);
            float s = 0.f;
            #pragma unroll
            for (int k = 0; k < 4; ++k) {
                float4 v = row[k];
                s += v.x * v.x + v.y * v.y + v.z * v.z + v.w * v.w;
            }
            s += __shfl_xor_sync(0xffffffffu, s, 1);
            s += __shfl_xor_sync(0xffffffffu, s, 2);
            if (part == 0) diag_sh[t] = 0.5f * s;
        }
        __syncthreads();

        // ---- main GEMM: 8 tokens x 4 j-pairs per thread, packed f32x2 FMA ----
        unsigned long long acc[8][4];
        #pragma unroll
        for (int i = 0; i < 8; ++i)
            #pragma unroll
            for (int jp = 0; jp < 4; ++jp) acc[i][jp] = 0ull;

        #pragma unroll 2
        for (int dc = 0; dc < 16; ++dc) {
            float4 xq[8];
            #pragma unroll
            for (int i = 0; i < 8; ++i)   // warp-uniform address -> smem broadcast
                xq[i] = *reinterpret_cast<const float4*>(&xsh[(tb + i) * D_DIM + dc * 4]);
            #pragma unroll
            for (int k = 0; k < 4; ++k) {
                const int d = dc * 4 + k;
                const unsigned long long* prow =
                    reinterpret_cast<const unsigned long long*>(&pT[d * J_DIM + jb]);
                unsigned long long pv[4];
                #pragma unroll
                for (int jp = 0; jp < 4; ++jp) pv[jp] = prow[jp];
                #pragma unroll
                for (int i = 0; i < 8; ++i) {
                    const float xs = (k == 0) ? xq[i].x : (k == 1) ? xq[i].y
                                   : (k == 2) ? xq[i].z : xq[i].w;
                    const unsigned long long xp = pack2(xs, xs);
                    #pragma unroll
                    for (int jp = 0; jp < 4; ++jp)
                        acc[i][jp] = fma2(xp, pv[jp], acc[i][jp]);
                }
            }
        }

        // ---- fused epilogue: ratio * (exp(dd - diag) + eps), coalesced stores ----
        #pragma unroll
        for (int i = 0; i < 8; ++i) {
            const int gt = t0 + tb + i;
            if (gt >= T) break;
            const float dv = diag_sh[tb + i];
            float r[8];
            #pragma unroll
            for (int jp = 0; jp < 4; ++jp) {
                float a0, a1;
                unpack2(acc[i][jp], a0, a1);
                r[2 * jp]     = 0.0625f * (__expf(a0 - dv) + 1e-4f);
                r[2 * jp + 1] = 0.0625f * (__expf(a1 - dv) + 1e-4f);
            }
            float4* o = reinterpret_cast<float4*>(out + (size_t)gt * J_DIM + jb);
            o[0] = make_float4(r[0], r[1], r[2], r[3]);
            o[1] = make_float4(r[4], r[5], r[6], r[7]);
        }
    }
}

extern "C" void kernel_launch(void* const* d_in, const int* in_sizes, int n_in,
                              void* d_out, int out_size) {
    const float* x    = (const float*)d_in[0];
    const float* proj = (const float*)d_in[1];
    float* out        = (float*)d_out;

    const int T      = in_sizes[0] / D_DIM;                  // total tokens
    const int nTiles = (T + TOK_TILE - 1) / TOK_TILE;
    const int smem_bytes =
        (D_DIM * J_DIM + TOK_TILE * D_DIM + TOK_TILE) * (int)sizeof(float);

    cudaFuncSetAttribute(performer_fm_r7_kernel,
                         cudaFuncAttributeMaxDynamicSharedMemorySize, smem_bytes);

    int grid = 296;                 // 2 CTAs/SM * 148 SMs
    if (grid > nTiles) grid = nTiles;
    performer_fm_r7_kernel<<<grid, NTHREADS, smem_bytes>>>(x, proj, out, T, nTiles);
}

// round 13
// speedup vs baseline: 1.8092x; 1.8092x over previous
#include <cuda_runtime.h>
#include <cuda_bf16.h>

// Performer FAVOR+ feature map — r12: bf16 mma.sync GEMM, B-fragment fix.
// R9 bug: B loaded with ldmatrix.trans; pT is [n][k] row-major so the
// m16n8k16 row.col B fragment needs NON-trans ldmatrix (consecutive-k pairs).
// out[t,j] = 1/16 * ( exp( x_t·(c*P_j) - 0.5||x_t||^2 ) + 1e-4 ), c = 64^-0.25

#define D_DIM 64
#define J_DIM 256
#define TOK_TILE 128
#define NTHREADS 512
#define ROW_PAD 72            // bf16 elems/row (64 + 8 pad) = 144 B

// smem byte offsets
#define SM_PT    0                         // [256][72] bf16 = 36864 B
#define SM_X     36864                     // 2 x [128][72] bf16 = 36864 B
#define SM_DIAG  (36864 + 36864)           // 2 x [128] fp32 = 1024 B
#define SM_TOTAL (36864 + 36864 + 1024)

__device__ __forceinline__ unsigned smem_u32(const void* p) {
    return (unsigned)__cvta_generic_to_shared(p);
}
__device__ __forceinline__ void ldsm_x4(unsigned addr, unsigned& r0, unsigned& r1,
                                        unsigned& r2, unsigned& r3) {
    asm volatile("ldmatrix.sync.aligned.m8n8.x4.shared.b16 {%0,%1,%2,%3}, [%4];"
                 : "=r"(r0), "=r"(r1), "=r"(r2), "=r"(r3) : "r"(addr));
}
__device__ __forceinline__ void mma_bf16(float& c0, float& c1, float& c2, float& c3,
                                         unsigned a0, unsigned a1, unsigned a2, unsigned a3,
                                         unsigned b0, unsigned b1) {
    asm volatile("mma.sync.aligned.m16n8k16.row.col.f32.bf16.bf16.f32 "
                 "{%0,%1,%2,%3}, {%4,%5,%6,%7}, {%8,%9}, {%0,%1,%2,%3};"
                 : "+f"(c0), "+f"(c1), "+f"(c2), "+f"(c3)
                 : "r"(a0), "r"(a1), "r"(a2), "r"(a3), "r"(b0), "r"(b1));
}

extern __shared__ char smem_raw[];

__global__ void __launch_bounds__(NTHREADS, 1)
performer_fm_mma_r12_kernel(const float* __restrict__ x,
                            const float* __restrict__ proj,
                            float* __restrict__ out,
                            int T, int nTiles)
{
    __nv_bfloat16* pT   = (__nv_bfloat16*)(smem_raw + SM_PT);    // [256][ROW_PAD]
    __nv_bfloat16* xsm  = (__nv_bfloat16*)(smem_raw + SM_X);     // [2][128][ROW_PAD]
    float*         diag = (float*)(smem_raw + SM_DIAG);          // [2][128]

    const int tid  = threadIdx.x;
    const int lane = tid & 31;
    const int warp = tid >> 5;
    const int tw   = (warp & 7) * 16;      // token-row base of this warp within tile
    const int jh   = warp >> 3;            // j half: 0 -> j 0..127, 1 -> j 128..255

    // ---- load projection once per (persistent) CTA: pT[j][d] = bf16(c * P[j][d])
    {
        const float c = 0.35355339059327373f;   // 64^(-1/4) folded into P
        const int j  = tid >> 1;
        const int dh = (tid & 1) * 32;
        const float4* src = (const float4*)(proj + j * D_DIM + dh);
        __nv_bfloat162* dst = (__nv_bfloat162*)(pT + j * ROW_PAD + dh);
        #pragma unroll
        for (int i = 0; i < 8; ++i) {
            float4 v = src[i];
            dst[2 * i]     = __floats2bfloat162_rn(c * v.x, c * v.y);
            dst[2 * i + 1] = __floats2bfloat162_rn(c * v.z, c * v.w);
        }
    }

    // staging: thread owns token t = tid/4, d-range part*16..+16 (16 floats)
    const int st = tid >> 2;
    const int sp = tid & 3;

    float4 stg[4];
    // prologue: load + commit tile0 into buffer 0
    {
        long gt = (long)blockIdx.x * TOK_TILE + st;
        if (blockIdx.x < nTiles && gt < T) {
            const float4* src = (const float4*)(x + gt * D_DIM + sp * 16);
            stg[0] = src[0]; stg[1] = src[1]; stg[2] = src[2]; stg[3] = src[3];
        } else {
            stg[0] = stg[1] = stg[2] = stg[3] = make_float4(0.f, 0.f, 0.f, 0.f);
        }
        float s = 0.f;
        __nv_bfloat162* dst = (__nv_bfloat162*)(xsm + st * ROW_PAD + sp * 16);
        #pragma unroll
        for (int i = 0; i < 4; ++i) {
            float4 v = stg[i];
            s += v.x * v.x + v.y * v.y + v.z * v.z + v.w * v.w;
            dst[2 * i]     = __floats2bfloat162_rn(v.x, v.y);
            dst[2 * i + 1] = __floats2bfloat162_rn(v.z, v.w);
        }
        s += __shfl_xor_sync(0xffffffffu, s, 1);
        s += __shfl_xor_sync(0xffffffffu, s, 2);
        if (sp == 0) diag[st] = 0.5f * s;
    }

    int buf = 0;
    for (int tile = blockIdx.x; tile < nTiles; tile += gridDim.x) {
        __syncthreads();   // xsm[buf], diag[buf] (and pT on iter 0) visible to all

        // ---- stage next tile's x into registers (latency hidden behind MMA)
        const int nxt = tile + gridDim.x;
        if (nxt < nTiles) {
            long gt = (long)nxt * TOK_TILE + st;
            const float4* src = (const float4*)(x + gt * D_DIM + sp * 16);
            if (gt < T) {
                stg[0] = src[0]; stg[1] = src[1]; stg[2] = src[2]; stg[3] = src[3];
            } else {
                stg[0] = stg[1] = stg[2] = stg[3] = make_float4(0.f, 0.f, 0.f, 0.f);
            }
        }

        // ---- A fragments for this warp's 16 token rows (K = 64, 4 k-chunks)
        unsigned a[4][4];
        {
            const __nv_bfloat16* xb = xsm + (size_t)buf * 128 * ROW_PAD;
            const int r  = tw + (lane & 15);
            const int kb = (lane >> 4) * 8;
            #pragma unroll
            for (int kc = 0; kc < 4; ++kc) {
                unsigned addr = smem_u32(xb + r * ROW_PAD + kc * 16 + kb);
                ldsm_x4(addr, a[kc][0], a[kc][1], a[kc][2], a[kc][3]);
            }
        }

        // epilogue constants
        const float* dg = diag + buf * 128;
        const float d0 = dg[tw + (lane >> 2)];
        const float d1 = dg[tw + (lane >> 2) + 8];
        const long  t0 = (long)tile * TOK_TILE;
        const long  r0 = t0 + tw + (lane >> 2);
        const long  r1 = r0 + 8;

        // ---- 16 j per pass: MMA over 4 k-chunks, then fused exp epilogue
        #pragma unroll
        for (int nb2 = 0; nb2 < 8; ++nb2) {
            float acc[2][4] = {{0.f, 0.f, 0.f, 0.f}, {0.f, 0.f, 0.f, 0.f}};
            const int nbase = jh * 128 + nb2 * 16;
            // four 8x8 tiles: (n0-7,k0-7)(n0-7,k8-15)(n8-15,k0-7)(n8-15,k8-15)
            const int n = nbase + (lane >> 4) * 8 + (lane & 7);
            #pragma unroll
            for (int kc = 0; kc < 4; ++kc) {
                const int k = kc * 16 + ((lane >> 3) & 1) * 8;
                unsigned b0, b1, b2, b3;
                // NON-trans: pT is [n][k] row-major -> consecutive-k pairs per reg,
                // exactly the row.col B fragment (flash-attn K-operand pattern).
                ldsm_x4(smem_u32(pT + n * ROW_PAD + k), b0, b1, b2, b3);
                mma_bf16(acc[0][0], acc[0][1], acc[0][2], acc[0][3],
                         a[kc][0], a[kc][1], a[kc][2], a[kc][3], b0, b1);
                mma_bf16(acc[1][0], acc[1][1], acc[1][2], acc[1][3],
                         a[kc][0], a[kc][1], a[kc][2], a[kc][3], b2, b3);
            }
            #pragma unroll
            for (int h = 0; h < 2; ++h) {
                const int j = nbase + h * 8 + (lane & 3) * 2;
                float e0 = 0.0625f * (__expf(acc[h][0] - d0) + 1e-4f);
                float e1 = 0.0625f * (__expf(acc[h][1] - d0) + 1e-4f);
                float e2 = 0.0625f * (__expf(acc[h][2] - d1) + 1e-4f);
                float e3 = 0.0625f * (__expf(acc[h][3] - d1) + 1e-4f);
                if (r0 < T) *(float2*)(out + r0 * J_DIM + j) = make_float2(e0, e1);
                if (r1 < T) *(float2*)(out + r1 * J_DIM + j) = make_float2(e2, e3);
            }
        }

        __syncthreads();   // all warps done reading xsm[buf] / diag[buf]

        // ---- commit staged x into the other buffer for the next tile
        if (nxt < nTiles) {
            float s = 0.f;
            __nv_bfloat162* dst = (__nv_bfloat162*)(xsm + (size_t)(buf ^ 1) * 128 * ROW_PAD
                                                    + st * ROW_PAD + sp * 16);
            #pragma unroll
            for (int i = 0; i < 4; ++i) {
                float4 v = stg[i];
                s += v.x * v.x + v.y * v.y + v.z * v.z + v.w * v.w;
                dst[2 * i]     = __floats2bfloat162_rn(v.x, v.y);
                dst[2 * i + 1] = __floats2bfloat162_rn(v.z, v.w);
            }
            s += __shfl_xor_sync(0xffffffffu, s, 1);
            s += __shfl_xor_sync(0xffffffffu, s, 2);
            if (sp == 0) diag[(buf ^ 1) * 128 + st] = 0.5f * s;
        }
        buf ^= 1;
    }
}

extern "C" void kernel_launch(void* const* d_in, const int* in_sizes, int n_in,
                              void* d_out, int out_size) {
    const float* x    = (const float*)d_in[0];
    const float* proj = (const float*)d_in[1];
    float* out        = (float*)d_out;

    const int T      = in_sizes[0] / D_DIM;
    const int nTiles = (T + TOK_TILE - 1) / TOK_TILE;

    cudaFuncSetAttribute(performer_fm_mma_r12_kernel,
                         cudaFuncAttributeMaxDynamicSharedMemorySize, SM_TOTAL);

    int grid = 148;                 // persistent: 1 CTA/SM (512 thr)
    if (grid > nTiles) grid = nTiles;
    performer_fm_mma_r12_kernel<<<grid, NTHREADS, SM_TOTAL>>>(x, proj, out, T, nTiles);
}

// round 17
// speedup vs baseline: 2.7677x; 1.5298x over previous
#include <cuda_runtime.h>
#include <cuda_bf16.h>

// Performer FAVOR+ feature map — r14: store repack via shfl -> STG.128,
// ratio folded into exponent, streaming load/store hints.
// R13 ncu: L1tex 78% (bound), stores were STG.64 scattered over 8 rows/warp
// (32B/line). shfl_xor(1) merges partner j-pairs -> float4 (64B/line), 2x
// fewer store wavefronts.
// out[t,j] = exp( x_t·(c*P_j) - 0.5||x_t||^2 - ln16 ) + 6.25e-6, c = 64^-0.25

#define D_DIM 64
#define J_DIM 256
#define TOK_TILE 128
#define NTHREADS 512
#define ROW_PAD 72            // bf16 elems/row (64 + 8 pad) = 144 B
#define LN16 2.772588722239781f
#define EPS16 6.25e-6f

// smem byte offsets
#define SM_PT    0                         // [256][72] bf16 = 36864 B
#define SM_X     36864                     // 2 x [128][72] bf16 = 36864 B
#define SM_DIAG  (36864 + 36864)           // 2 x [128] fp32 = 1024 B
#define SM_TOTAL (36864 + 36864 + 1024)

__device__ __forceinline__ unsigned smem_u32(const void* p) {
    return (unsigned)__cvta_generic_to_shared(p);
}
__device__ __forceinline__ void ldsm_x4(unsigned addr, unsigned& r0, unsigned& r1,
                                        unsigned& r2, unsigned& r3) {
    asm volatile("ldmatrix.sync.aligned.m8n8.x4.shared.b16 {%0,%1,%2,%3}, [%4];"
                 : "=r"(r0), "=r"(r1), "=r"(r2), "=r"(r3) : "r"(addr));
}
__device__ __forceinline__ void mma_bf16(float& c0, float& c1, float& c2, float& c3,
                                         unsigned a0, unsigned a1, unsigned a2, unsigned a3,
                                         unsigned b0, unsigned b1) {
    asm volatile("mma.sync.aligned.m16n8k16.row.col.f32.bf16.bf16.f32 "
                 "{%0,%1,%2,%3}, {%4,%5,%6,%7}, {%8,%9}, {%0,%1,%2,%3};"
                 : "+f"(c0), "+f"(c1), "+f"(c2), "+f"(c3)
                 : "r"(a0), "r"(a1), "r"(a2), "r"(a3), "r"(b0), "r"(b1));
}

extern __shared__ char smem_raw[];

__global__ void __launch_bounds__(NTHREADS, 1)
performer_fm_mma_r14_kernel(const float* __restrict__ x,
                            const float* __restrict__ proj,
                            float* __restrict__ out,
                            int T, int nTiles)
{
    __nv_bfloat16* pT   = (__nv_bfloat16*)(smem_raw + SM_PT);    // [256][ROW_PAD]
    __nv_bfloat16* xsm  = (__nv_bfloat16*)(smem_raw + SM_X);     // [2][128][ROW_PAD]
    float*         diag = (float*)(smem_raw + SM_DIAG);          // [2][128]

    const int tid  = threadIdx.x;
    const int lane = tid & 31;
    const int warp = tid >> 5;
    const int tw   = (warp & 7) * 16;      // token-row base of this warp within tile
    const int jh   = warp >> 3;            // j half: 0 -> j 0..127, 1 -> j 128..255
    const bool evn = !(lane & 1);
    // j offset of this thread's float4 within its 16-wide nb2 block
    const int joff = ((lane & 1) ? 8 : 0) + (lane & 2) * 2;

    // ---- load projection once per (persistent) CTA: pT[j][d] = bf16(c * P[j][d])
    {
        const float c = 0.35355339059327373f;   // 64^(-1/4) folded into P
        const int j  = tid >> 1;
        const int dh = (tid & 1) * 32;
        const float4* src = (const float4*)(proj + j * D_DIM + dh);
        __nv_bfloat162* dst = (__nv_bfloat162*)(pT + j * ROW_PAD + dh);
        #pragma unroll
        for (int i = 0; i < 8; ++i) {
            float4 v = src[i];
            dst[2 * i]     = __floats2bfloat162_rn(c * v.x, c * v.y);
            dst[2 * i + 1] = __floats2bfloat162_rn(c * v.z, c * v.w);
        }
    }

    // staging: thread owns token t = tid/4, d-range part*16..+16 (16 floats)
    const int st = tid >> 2;
    const int sp = tid & 3;

    float4 stg[4];
    // prologue: load + commit tile0 into buffer 0
    {
        long gt = (long)blockIdx.x * TOK_TILE + st;
        if (blockIdx.x < nTiles && gt < T) {
            const float4* src = (const float4*)(x + gt * D_DIM + sp * 16);
            stg[0] = __ldcs(src); stg[1] = __ldcs(src + 1);
            stg[2] = __ldcs(src + 2); stg[3] = __ldcs(src + 3);
        } else {
            stg[0] = stg[1] = stg[2] = stg[3] = make_float4(0.f, 0.f, 0.f, 0.f);
        }
        float s = 0.f;
        __nv_bfloat162* dst = (__nv_bfloat162*)(xsm + st * ROW_PAD + sp * 16);
        #pragma unroll
        for (int i = 0; i < 4; ++i) {
            float4 v = stg[i];
            s += v.x * v.x + v.y * v.y + v.z * v.z + v.w * v.w;
            dst[2 * i]     = __floats2bfloat162_rn(v.x, v.y);
            dst[2 * i + 1] = __floats2bfloat162_rn(v.z, v.w);
        }
        s += __shfl_xor_sync(0xffffffffu, s, 1);
        s += __shfl_xor_sync(0xffffffffu, s, 2);
        if (sp == 0) diag[st] = 0.5f * s;
    }

    int buf = 0;
    for (int tile = blockIdx.x; tile < nTiles; tile += gridDim.x) {
        __syncthreads();   // xsm[buf], diag[buf] (and pT on iter 0) visible to all

        // ---- stage next tile's x into registers (latency hidden behind MMA)
        const int nxt = tile + gridDim.x;
        if (nxt < nTiles) {
            long gt = (long)nxt * TOK_TILE + st;
            const float4* src = (const float4*)(x + gt * D_DIM + sp * 16);
            if (gt < T) {
                stg[0] = __ldcs(src); stg[1] = __ldcs(src + 1);
                stg[2] = __ldcs(src + 2); stg[3] = __ldcs(src + 3);
            } else {
                stg[0] = stg[1] = stg[2] = stg[3] = make_float4(0.f, 0.f, 0.f, 0.f);
            }
        }

        // ---- A fragments for this warp's 16 token rows (K = 64, 4 k-chunks)
        unsigned a[4][4];
        {
            const __nv_bfloat16* xb = xsm + (size_t)buf * 128 * ROW_PAD;
            const int r  = tw + (lane & 15);
            const int kb = (lane >> 4) * 8;
            #pragma unroll
            for (int kc = 0; kc < 4; ++kc) {
                unsigned addr = smem_u32(xb + r * ROW_PAD + kc * 16 + kb);
                ldsm_x4(addr, a[kc][0], a[kc][1], a[kc][2], a[kc][3]);
            }
        }

        // epilogue constants (ln16 folded into diag)
        const float* dg = diag + buf * 128;
        const float d0 = dg[tw + (lane >> 2)] + LN16;
        const float d1 = dg[tw + (lane >> 2) + 8] + LN16;
        const long  t0 = (long)tile * TOK_TILE;
        const long  r0 = t0 + tw + (lane >> 2);
        const long  r1 = r0 + 8;

        // ---- 16 j per pass: MMA over 4 k-chunks, then fused exp epilogue
        #pragma unroll
        for (int nb2 = 0; nb2 < 8; ++nb2) {
            float acc[2][4] = {{0.f, 0.f, 0.f, 0.f}, {0.f, 0.f, 0.f, 0.f}};
            const int nbase = jh * 128 + nb2 * 16;
            // four 8x8 tiles: (n0-7,k0-7)(n0-7,k8-15)(n8-15,k0-7)(n8-15,k8-15)
            const int n = nbase + (lane >> 4) * 8 + (lane & 7);
            #pragma unroll
            for (int kc = 0; kc < 4; ++kc) {
                const int k = kc * 16 + ((lane >> 3) & 1) * 8;
                unsigned b0, b1, b2, b3;
                ldsm_x4(smem_u32(pT + n * ROW_PAD + k), b0, b1, b2, b3);
                mma_bf16(acc[0][0], acc[0][1], acc[0][2], acc[0][3],
                         a[kc][0], a[kc][1], a[kc][2], a[kc][3], b0, b1);
                mma_bf16(acc[1][0], acc[1][1], acc[1][2], acc[1][3],
                         a[kc][0], a[kc][1], a[kc][2], a[kc][3], b2, b3);
            }

            // ---- repack: partner-exchange h0/h1 j-pairs -> one float4 per row
            // even lane sends its h1 pair, odd sends its h0 pair; after xor(1):
            //   even: (own h0, partner h0) = j nbase+(lane&2)*2 .. +3      (row r0/r1)
            //   odd : (partner h1, own h1) = j nbase+8+(lane&2)*2 .. +3
            float s0 = evn ? acc[1][0] : acc[0][0];
            float s1 = evn ? acc[1][1] : acc[0][1];
            float s2 = evn ? acc[1][2] : acc[0][2];
            float s3 = evn ? acc[1][3] : acc[0][3];
            float g0 = __shfl_xor_sync(0xffffffffu, s0, 1);
            float g1 = __shfl_xor_sync(0xffffffffu, s1, 1);
            float g2 = __shfl_xor_sync(0xffffffffu, s2, 1);
            float g3 = __shfl_xor_sync(0xffffffffu, s3, 1);
            float k0 = evn ? acc[0][0] : acc[1][0];
            float k1 = evn ? acc[0][1] : acc[1][1];
            float k2 = evn ? acc[0][2] : acc[1][2];
            float k3 = evn ? acc[0][3] : acc[1][3];

            // ordered j, j+1, j+2, j+3
            float u0 = evn ? k0 : g0, u1 = evn ? k1 : g1;
            float u2 = evn ? g0 : k0, u3 = evn ? g1 : k1;      // row r0
            float v0 = evn ? k2 : g2, v1 = evn ? k3 : g3;
            float v2 = evn ? g2 : k2, v3 = evn ? g3 : k3;      // row r1

            const int j = nbase + joff;
            float4 o0 = make_float4(__expf(u0 - d0) + EPS16, __expf(u1 - d0) + EPS16,
                                    __expf(u2 - d0) + EPS16, __expf(u3 - d0) + EPS16);
            float4 o1 = make_float4(__expf(v0 - d1) + EPS16, __expf(v1 - d1) + EPS16,
                                    __expf(v2 - d1) + EPS16, __expf(v3 - d1) + EPS16);
            if (r0 < T) __stcs((float4*)(out + r0 * J_DIM + j), o0);
            if (r1 < T) __stcs((float4*)(out + r1 * J_DIM + j), o1);
        }

        __syncthreads();   // all warps done reading xsm[buf] / diag[buf]

        // ---- commit staged x into the other buffer for the next tile
        if (nxt < nTiles) {
            float s = 0.f;
            __nv_bfloat162* dst = (__nv_bfloat162*)(xsm + (size_t)(buf ^ 1) * 128 * ROW_PAD
                                                    + st * ROW_PAD + sp * 16);
            #pragma unroll
            for (int i = 0; i < 4; ++i) {
                float4 v = stg[i];
                s += v.x * v.x + v.y * v.y + v.z * v.z + v.w * v.w;
                dst[2 * i]     = __floats2bfloat162_rn(v.x, v.y);
                dst[2 * i + 1] = __floats2bfloat162_rn(v.z, v.w);
            }
            s += __shfl_xor_sync(0xffffffffu, s, 1);
            s += __shfl_xor_sync(0xffffffffu, s, 2);
            if (sp == 0) diag[(buf ^ 1) * 128 + st] = 0.5f * s;
        }
        buf ^= 1;
    }
}

extern "C" void kernel_launch(void* const* d_in, const int* in_sizes, int n_in,
                              void* d_out, int out_size) {
    const float* x    = (const float*)d_in[0];
    const float* proj = (const float*)d_in[1];
    float* out        = (float*)d_out;

    const int T      = in_sizes[0] / D_DIM;
    const int nTiles = (T + TOK_TILE - 1) / TOK_TILE;

    cudaFuncSetAttribute(performer_fm_mma_r14_kernel,
                         cudaFuncAttributeMaxDynamicSharedMemorySize, SM_TOTAL);

    int grid = 148;                 // persistent: 1 CTA/SM (512 thr)
    if (grid > nTiles) grid = nTiles;
    performer_fm_mma_r14_kernel<<<grid, NTHREADS, SM_TOTAL>>>(x, proj, out, T, nTiles);
}